// round 6
// baseline (speedup 1.0000x reference)
#include <cuda_runtime.h>
#include <cuda_bf16.h>
#include <math.h>

#define N_VIEWS   512
#define N_MULTI   32
#define MAX_SIFT  2048
#define N_MATCHES 1000000

#define FEAT_ELEMS (N_VIEWS * MAX_SIFT * 3)   // 3,145,728
#define FLAT_ROWS  (N_VIEWS * MAX_SIFT)       // 1,048,576

__device__ __forceinline__ void mat33_mul(const float* __restrict__ A,
                                          const float* __restrict__ B,
                                          float* __restrict__ C)
{
    // C = A @ B, row-major
    #pragma unroll
    for (int r = 0; r < 3; r++)
        #pragma unroll
        for (int c = 0; c < 3; c++)
            C[r * 3 + c] = fmaf(A[r * 3 + 0], B[0 * 3 + c],
                           fmaf(A[r * 3 + 1], B[1 * 3 + c],
                                A[r * 3 + 2] * B[2 * 3 + c]));
}

// ---------------------------------------------------------------------------
// Fused kernel: per-block prefix reduction (rot product + c_3 cumsum up to
// view v) followed by the streaming beta-weighted sum + rotation.
//
// feat[v,s,:] = (sum_m beta[v,m]*pdepth[v,:,m,s] + pdepth0[v,:,s]) @ R_v + T_v
//   R_v = rot_0 @ rot_1 @ ... @ rot_v       (left-to-right)
//   T_v = sum_{u<=v} c_3[u]
//
// Grid = 4 blocks per view x 128 threads. Each thread owns one float4 column.
// Streaming inputs use __ldcs (evict-first) to keep feat resident in L2 for
// the delta gather.
// ---------------------------------------------------------------------------
__global__ void __launch_bounds__(128)
feat_kernel(const float* __restrict__ euler,     // (512,3)
            const float* __restrict__ c_3,       // (512,1,3)
            const float* __restrict__ beta,      // (512,1,1,32)
            const float* __restrict__ pdepth,    // (512,3,32,2048)
            const float* __restrict__ pdepth0,   // (512,3,1,2048)
            float* __restrict__ feat)            // (512,2048,3)
{
    const int v     = blockIdx.x >> 2;
    const int chunk = blockIdx.x & 3;
    const int tid   = threadIdx.x;
    const int q     = chunk * 128 + tid;   // quad index within view

    // ---- Prologue: compute (R_v, T_v) with a 128-way ordered tree reduce ----
    __shared__ float red[128][12];   // [0..8]=matrix, [9..11]=translation
    __shared__ float sb[N_MULTI];

    {
        float M[9] = {1.f, 0.f, 0.f, 0.f, 1.f, 0.f, 0.f, 0.f, 1.f};
        float T3[3] = {0.f, 0.f, 0.f};
        const int base = tid * 4;
        #pragma unroll
        for (int k = 0; k < 4; k++) {
            const int view = base + k;
            if (view <= v) {
                float a = euler[view * 3 + 0];
                float b = euler[view * 3 + 1];
                float c = euler[view * 3 + 2];
                float sa, ca, sb_, cb, sc, cc;
                __sincosf(a, &sa, &ca);
                __sincosf(b, &sb_, &cb);
                __sincosf(c, &sc, &cc);
                float R[9];
                R[0] = ca * cc + sa * sb_ * sc;
                R[1] = -sa * cb;
                R[2] = -ca * sc + sa * sb_ * cc;
                R[3] = sa * cc - ca * sb_ * sc;
                R[4] = ca * cb;
                R[5] = -sa * sc - ca * sb_ * cc;
                R[6] = cb * sc;
                R[7] = sb_;
                R[8] = cb * cc;
                float C[9];
                mat33_mul(M, R, C);
                #pragma unroll
                for (int j = 0; j < 9; j++) M[j] = C[j];
                T3[0] += c_3[view * 3 + 0];
                T3[1] += c_3[view * 3 + 1];
                T3[2] += c_3[view * 3 + 2];
            }
        }
        #pragma unroll
        for (int j = 0; j < 9; j++) red[tid][j] = M[j];
        red[tid][9] = T3[0]; red[tid][10] = T3[1]; red[tid][11] = T3[2];

        // left-to-right pairwise tree: after level s, tid covers [4*tid, 4*tid + 8s)
        #pragma unroll
        for (int s = 1; s < 128; s <<= 1) {
            __syncthreads();
            if ((tid & (2 * s - 1)) == 0) {
                float A[9], B[9], C[9];
                #pragma unroll
                for (int j = 0; j < 9; j++) { A[j] = red[tid][j]; B[j] = red[tid + s][j]; }
                mat33_mul(A, B, C);
                #pragma unroll
                for (int j = 0; j < 9; j++) red[tid][j] = C[j];
                red[tid][9]  += red[tid + s][9];
                red[tid][10] += red[tid + s][10];
                red[tid][11] += red[tid + s][11];
            }
        }

        if (tid < N_MULTI) sb[tid] = beta[v * N_MULTI + tid];
        __syncthreads();
    }

    const float sR0 = red[0][0], sR1 = red[0][1], sR2 = red[0][2];
    const float sR3 = red[0][3], sR4 = red[0][4], sR5 = red[0][5];
    const float sR6 = red[0][6], sR7 = red[0][7], sR8 = red[0][8];
    const float sT0 = red[0][9], sT1 = red[0][10], sT2 = red[0][11];

    // ---- Mainloop: stream pdepth, accumulate beta-weighted sum ----
    const float4* p0 = (const float4*)(pdepth0 + (size_t)v * 3 * MAX_SIFT);
    float4 acc[3];
    #pragma unroll
    for (int ch = 0; ch < 3; ch++)
        acc[ch] = __ldcs(&p0[(size_t)ch * (MAX_SIFT / 4) + q]);

    const float4* pd = (const float4*)(pdepth + (size_t)v * 3 * N_MULTI * MAX_SIFT);
    #pragma unroll
    for (int m = 0; m < N_MULTI; m++) {
        float bm = sb[m];
        #pragma unroll
        for (int ch = 0; ch < 3; ch++) {
            float4 p = __ldcs(&pd[((size_t)ch * N_MULTI + m) * (MAX_SIFT / 4) + q]);
            acc[ch].x = fmaf(bm, p.x, acc[ch].x);
            acc[ch].y = fmaf(bm, p.y, acc[ch].y);
            acc[ch].z = fmaf(bm, p.z, acc[ch].z);
            acc[ch].w = fmaf(bm, p.w, acc[ch].w);
        }
    }

    // ---- Epilogue: rotate + translate, packed float4 stores ----
    float o[4][3];
    const float ax[4] = {acc[0].x, acc[0].y, acc[0].z, acc[0].w};
    const float ay[4] = {acc[1].x, acc[1].y, acc[1].z, acc[1].w};
    const float az[4] = {acc[2].x, acc[2].y, acc[2].z, acc[2].w};
    #pragma unroll
    for (int e = 0; e < 4; e++) {
        o[e][0] = fmaf(ax[e], sR0, fmaf(ay[e], sR3, fmaf(az[e], sR6, sT0)));
        o[e][1] = fmaf(ax[e], sR1, fmaf(ay[e], sR4, fmaf(az[e], sR7, sT1)));
        o[e][2] = fmaf(ax[e], sR2, fmaf(ay[e], sR5, fmaf(az[e], sR8, sT2)));
    }

    // 12 consecutive floats at feat + v*6144 + q*12 (48B, 16B-aligned)
    float4* out = (float4*)(feat + (size_t)v * MAX_SIFT * 3) + (size_t)q * 3;
    out[0] = make_float4(o[0][0], o[0][1], o[0][2], o[1][0]);
    out[1] = make_float4(o[1][1], o[1][2], o[2][0], o[2][1]);
    out[2] = make_float4(o[2][2], o[3][0], o[3][1], o[3][2]);
}

// ---------------------------------------------------------------------------
// delta[t] = || feat_flat[m0] - feat_flat[m1] ||
// matches is int32 (JAX x64-disabled downcast). feat is L2-resident.
// ---------------------------------------------------------------------------
__global__ void __launch_bounds__(256)
delta_kernel(const int* __restrict__ matches,   // (1e6, 2) int32
             const float* __restrict__ feat,
             float* __restrict__ delta)
{
    const int t = blockIdx.x * blockDim.x + threadIdx.x;
    if (t >= N_MATCHES) return;

    int2 m = ((const int2*)matches)[t];
    unsigned i0 = (unsigned)m.x % FLAT_ROWS;
    unsigned i1 = (unsigned)m.y % FLAT_ROWS;
    const float* p0 = feat + (size_t)i0 * 3;
    const float* p1 = feat + (size_t)i1 * 3;
    float dx = __ldg(p0 + 0) - __ldg(p1 + 0);
    float dy = __ldg(p0 + 1) - __ldg(p1 + 1);
    float dz = __ldg(p0 + 2) - __ldg(p1 + 2);
    delta[t] = sqrtf(fmaf(dx, dx, fmaf(dy, dy, dz * dz)));
}

// ---------------------------------------------------------------------------
extern "C" void kernel_launch(void* const* d_in, const int* in_sizes, int n_in,
                              void* d_out, int out_size)
{
    const float* euler   = (const float*)d_in[0];   // c33_euler (512,3)
    const float* c_3     = (const float*)d_in[1];   // (512,1,3)
    const float* beta    = (const float*)d_in[2];   // (512,1,1,32)
    const float* pdepth  = (const float*)d_in[3];   // (512,3,32,2048)
    const float* pdepth0 = (const float*)d_in[4];   // (512,3,1,2048)
    const int*   matches = (const int*)d_in[5];     // (1e6,2) int32

    float* feat  = (float*)d_out;              // first 3,145,728 floats
    float* delta = feat + FEAT_ELEMS;          // next 1,000,000 floats

    feat_kernel<<<N_VIEWS * 4, 128>>>(euler, c_3, beta, pdepth, pdepth0, feat);
    delta_kernel<<<(N_MATCHES + 255) / 256, 256>>>(matches, feat, delta);
}

// round 7
// speedup vs baseline: 1.0737x; 1.0737x over previous
#include <cuda_runtime.h>
#include <cuda_bf16.h>
#include <math.h>

#define N_VIEWS   512
#define N_MULTI   32
#define MAX_SIFT  2048
#define N_MATCHES 1000000

#define FEAT_ELEMS (N_VIEWS * MAX_SIFT * 3)   // 3,145,728
#define FLAT_ROWS  (N_VIEWS * MAX_SIFT)       // 1,048,576

// Per-view cumulative rotation (row-major 3x3) and translation.
__device__ float g_c33[N_VIEWS * 9];
__device__ float g_c3[N_VIEWS * 3];
// Padded 16B-per-point mirror of feat for the delta gather (1 sector/point,
// float4 loads -> 3x fewer L1tex wavefronts than 3 scalar gathers).
__device__ float4 g_feat4[FLAT_ROWS];

// ---------------------------------------------------------------------------
// Kernel 1: rotations + prefix matmul scan + cumsum(c_3).
// Two-level scan: warp-level Kogge-Stone via shuffles, then warp-0 scan of the
// 16 warp aggregates, then combine. One block of 512 threads.
// ---------------------------------------------------------------------------
__device__ __forceinline__ void mat33_mul(const float* __restrict__ A,
                                          const float* __restrict__ B,
                                          float* __restrict__ C)
{
    // C = A @ B, row-major
    #pragma unroll
    for (int r = 0; r < 3; r++)
        #pragma unroll
        for (int c = 0; c < 3; c++)
            C[r * 3 + c] = fmaf(A[r * 3 + 0], B[0 * 3 + c],
                           fmaf(A[r * 3 + 1], B[1 * 3 + c],
                                A[r * 3 + 2] * B[2 * 3 + c]));
}

__global__ void __launch_bounds__(512)
scan_kernel(const float* __restrict__ euler,   // (512,3)
            const float* __restrict__ c_3)     // (512,1,3)
{
    const int i    = threadIdx.x;     // view index
    const int lane = i & 31;
    const int warp = i >> 5;          // 0..15

    float a = euler[i * 3 + 0];
    float b = euler[i * 3 + 1];
    float c = euler[i * 3 + 2];
    float sa, ca, sb, cb, sc, cc;
    sincosf(a, &sa, &ca);
    sincosf(b, &sb, &cb);
    sincosf(c, &sc, &cc);

    float M[9], T[3];
    M[0] = ca * cc + sa * sb * sc;
    M[1] = -sa * cb;
    M[2] = -ca * sc + sa * sb * cc;
    M[3] = sa * cc - ca * sb * sc;
    M[4] = ca * cb;
    M[5] = -sa * sc - ca * sb * cc;
    M[6] = cb * sc;
    M[7] = sb;
    M[8] = cb * cc;
    T[0] = c_3[i * 3 + 0];
    T[1] = c_3[i * 3 + 1];
    T[2] = c_3[i * 3 + 2];

    // Phase 1: inclusive Kogge-Stone scan within each warp (earlier on left)
    #pragma unroll
    for (int d = 1; d < 32; d <<= 1) {
        float A[9], t0, t1, t2;
        #pragma unroll
        for (int k = 0; k < 9; k++) A[k] = __shfl_up_sync(0xffffffffu, M[k], d);
        t0 = __shfl_up_sync(0xffffffffu, T[0], d);
        t1 = __shfl_up_sync(0xffffffffu, T[1], d);
        t2 = __shfl_up_sync(0xffffffffu, T[2], d);
        if (lane >= d) {
            float C[9];
            mat33_mul(A, M, C);
            #pragma unroll
            for (int k = 0; k < 9; k++) M[k] = C[k];
            T[0] += t0; T[1] += t1; T[2] += t2;
        }
    }

    // Phase 2: warp 0 scans the 16 warp aggregates
    __shared__ float aggM[16][9];
    __shared__ float aggT[16][3];
    if (lane == 31) {
        #pragma unroll
        for (int k = 0; k < 9; k++) aggM[warp][k] = M[k];
        aggT[warp][0] = T[0]; aggT[warp][1] = T[1]; aggT[warp][2] = T[2];
    }
    __syncthreads();

    if (warp == 0) {
        float Ma[9] = {1.f, 0.f, 0.f, 0.f, 1.f, 0.f, 0.f, 0.f, 1.f};
        float Ta[3] = {0.f, 0.f, 0.f};
        if (lane < 16) {
            #pragma unroll
            for (int k = 0; k < 9; k++) Ma[k] = aggM[lane][k];
            Ta[0] = aggT[lane][0]; Ta[1] = aggT[lane][1]; Ta[2] = aggT[lane][2];
        }
        #pragma unroll
        for (int d = 1; d < 16; d <<= 1) {
            float A[9], t0, t1, t2;
            #pragma unroll
            for (int k = 0; k < 9; k++) A[k] = __shfl_up_sync(0xffffffffu, Ma[k], d);
            t0 = __shfl_up_sync(0xffffffffu, Ta[0], d);
            t1 = __shfl_up_sync(0xffffffffu, Ta[1], d);
            t2 = __shfl_up_sync(0xffffffffu, Ta[2], d);
            if (lane >= d && lane < 16) {
                float C[9];
                mat33_mul(A, Ma, C);
                #pragma unroll
                for (int k = 0; k < 9; k++) Ma[k] = C[k];
                Ta[0] += t0; Ta[1] += t1; Ta[2] += t2;
            }
        }
        if (lane < 16) {
            #pragma unroll
            for (int k = 0; k < 9; k++) aggM[lane][k] = Ma[k];
            aggT[lane][0] = Ta[0]; aggT[lane][1] = Ta[1]; aggT[lane][2] = Ta[2];
        }
    }
    __syncthreads();

    // Phase 3: combine — prefix of warps 0..w-1 applied on the left
    if (warp > 0) {
        float P[9], C[9];
        #pragma unroll
        for (int k = 0; k < 9; k++) P[k] = aggM[warp - 1][k];
        mat33_mul(P, M, C);
        #pragma unroll
        for (int k = 0; k < 9; k++) M[k] = C[k];
        T[0] += aggT[warp - 1][0];
        T[1] += aggT[warp - 1][1];
        T[2] += aggT[warp - 1][2];
    }

    #pragma unroll
    for (int k = 0; k < 9; k++) g_c33[i * 9 + k] = M[k];
    g_c3[i * 3 + 0] = T[0];
    g_c3[i * 3 + 1] = T[1];
    g_c3[i * 3 + 2] = T[2];
}

// ---------------------------------------------------------------------------
// Kernel 2: feat[v,s,:] = (sum_m beta[v,m]*pdepth[v,:,m,s] + pdepth0[v,:,s]) @ c33[v] + c3[v]
// Grid = 4 blocks per view x 128 threads; each thread owns one float4 column.
// Streaming inputs use __ldcs. Also writes the padded g_feat4 mirror.
// ---------------------------------------------------------------------------
__global__ void __launch_bounds__(128)
feat_kernel(const float* __restrict__ beta,      // (512,1,1,32)
            const float* __restrict__ pdepth,    // (512,3,32,2048)
            const float* __restrict__ pdepth0,   // (512,3,1,2048)
            float* __restrict__ feat)            // (512,2048,3)
{
    const int v     = blockIdx.x >> 2;
    const int chunk = blockIdx.x & 3;
    const int q     = chunk * 128 + threadIdx.x;   // quad index within view

    __shared__ float sb[N_MULTI];
    __shared__ float sR[9];
    __shared__ float sT[3];

    if (threadIdx.x < N_MULTI) sb[threadIdx.x] = beta[v * N_MULTI + threadIdx.x];
    if (threadIdx.x >= 32 && threadIdx.x < 41) sR[threadIdx.x - 32] = g_c33[v * 9 + (threadIdx.x - 32)];
    if (threadIdx.x >= 64 && threadIdx.x < 67) sT[threadIdx.x - 64] = g_c3[v * 3 + (threadIdx.x - 64)];
    __syncthreads();

    // accumulators per channel (x,y,z), 4 sifts wide
    const float4* p0 = (const float4*)(pdepth0 + (size_t)v * 3 * MAX_SIFT);
    float4 acc[3];
    #pragma unroll
    for (int ch = 0; ch < 3; ch++)
        acc[ch] = __ldcs(&p0[(size_t)ch * (MAX_SIFT / 4) + q]);

    const float4* pd = (const float4*)(pdepth + (size_t)v * 3 * N_MULTI * MAX_SIFT);
    #pragma unroll
    for (int m = 0; m < N_MULTI; m++) {
        float bm = sb[m];
        #pragma unroll
        for (int ch = 0; ch < 3; ch++) {
            float4 p = __ldcs(&pd[((size_t)ch * N_MULTI + m) * (MAX_SIFT / 4) + q]);
            acc[ch].x = fmaf(bm, p.x, acc[ch].x);
            acc[ch].y = fmaf(bm, p.y, acc[ch].y);
            acc[ch].z = fmaf(bm, p.z, acc[ch].z);
            acc[ch].w = fmaf(bm, p.w, acc[ch].w);
        }
    }

    // rotate + translate
    float o[4][3];
    const float ax[4] = {acc[0].x, acc[0].y, acc[0].z, acc[0].w};
    const float ay[4] = {acc[1].x, acc[1].y, acc[1].z, acc[1].w};
    const float az[4] = {acc[2].x, acc[2].y, acc[2].z, acc[2].w};
    #pragma unroll
    for (int e = 0; e < 4; e++) {
        o[e][0] = fmaf(ax[e], sR[0], fmaf(ay[e], sR[3], fmaf(az[e], sR[6], sT[0])));
        o[e][1] = fmaf(ax[e], sR[1], fmaf(ay[e], sR[4], fmaf(az[e], sR[7], sT[1])));
        o[e][2] = fmaf(ax[e], sR[2], fmaf(ay[e], sR[5], fmaf(az[e], sR[8], sT[2])));
    }

    // Required output layout: 12 consecutive floats (48B, 16B-aligned)
    float4* out = (float4*)(feat + (size_t)v * MAX_SIFT * 3) + (size_t)q * 3;
    out[0] = make_float4(o[0][0], o[0][1], o[0][2], o[1][0]);
    out[1] = make_float4(o[1][1], o[1][2], o[2][0], o[2][1]);
    out[2] = make_float4(o[2][2], o[3][0], o[3][1], o[3][2]);

    // Padded mirror for the gather: one aligned float4 per point
    float4* f4 = g_feat4 + (size_t)v * MAX_SIFT + (size_t)q * 4;
    f4[0] = make_float4(o[0][0], o[0][1], o[0][2], 0.f);
    f4[1] = make_float4(o[1][0], o[1][1], o[1][2], 0.f);
    f4[2] = make_float4(o[2][0], o[2][1], o[2][2], 0.f);
    f4[3] = make_float4(o[3][0], o[3][1], o[3][2], 0.f);
}

// ---------------------------------------------------------------------------
// Kernel 3: delta[t] = || feat4[m0] - feat4[m1] || via aligned float4 gathers.
// matches is int32 (JAX x64-disabled downcast). g_feat4 is L2-resident.
// ---------------------------------------------------------------------------
__global__ void __launch_bounds__(256)
delta_kernel(const int* __restrict__ matches,   // (1e6, 2) int32
             float* __restrict__ delta)
{
    const int t = blockIdx.x * blockDim.x + threadIdx.x;
    if (t >= N_MATCHES) return;

    int2 m = ((const int2*)matches)[t];
    unsigned i0 = (unsigned)m.x % FLAT_ROWS;
    unsigned i1 = (unsigned)m.y % FLAT_ROWS;
    float4 a = __ldg(&g_feat4[i0]);
    float4 b = __ldg(&g_feat4[i1]);
    float dx = a.x - b.x;
    float dy = a.y - b.y;
    float dz = a.z - b.z;
    delta[t] = sqrtf(fmaf(dx, dx, fmaf(dy, dy, dz * dz)));
}

// ---------------------------------------------------------------------------
extern "C" void kernel_launch(void* const* d_in, const int* in_sizes, int n_in,
                              void* d_out, int out_size)
{
    const float* euler   = (const float*)d_in[0];   // c33_euler (512,3)
    const float* c_3     = (const float*)d_in[1];   // (512,1,3)
    const float* beta    = (const float*)d_in[2];   // (512,1,1,32)
    const float* pdepth  = (const float*)d_in[3];   // (512,3,32,2048)
    const float* pdepth0 = (const float*)d_in[4];   // (512,3,1,2048)
    const int*   matches = (const int*)d_in[5];     // (1e6,2) int32

    float* feat  = (float*)d_out;              // first 3,145,728 floats
    float* delta = feat + FEAT_ELEMS;          // next 1,000,000 floats

    scan_kernel<<<1, N_VIEWS>>>(euler, c_3);
    feat_kernel<<<N_VIEWS * 4, 128>>>(beta, pdepth, pdepth0, feat);
    delta_kernel<<<(N_MATCHES + 255) / 256, 256>>>(matches, delta);
}

// round 8
// speedup vs baseline: 1.0944x; 1.0193x over previous
#include <cuda_runtime.h>
#include <cuda_bf16.h>
#include <math.h>

#define N_VIEWS   512
#define N_MULTI   32
#define MAX_SIFT  2048
#define N_MATCHES 1000000

#define FEAT_ELEMS (N_VIEWS * MAX_SIFT * 3)   // 3,145,728
#define FLAT_ROWS  (N_VIEWS * MAX_SIFT)       // 1,048,576

// Per-view cumulative rotation (row-major 3x3) and translation.
__device__ float g_c33[N_VIEWS * 9];
__device__ float g_c3[N_VIEWS * 3];
// Padded 16B-per-point mirror of feat for the delta gather (1 sector/point).
__device__ float4 g_feat4[FLAT_ROWS];

// ---------------------------------------------------------------------------
// Kernel 1: rotations + prefix matmul scan + cumsum(c_3).
// Two-level scan: warp-level Kogge-Stone via shuffles, then warp-0 scan of the
// 16 warp aggregates, then combine. One block of 512 threads.
// ---------------------------------------------------------------------------
__device__ __forceinline__ void mat33_mul(const float* __restrict__ A,
                                          const float* __restrict__ B,
                                          float* __restrict__ C)
{
    // C = A @ B, row-major
    #pragma unroll
    for (int r = 0; r < 3; r++)
        #pragma unroll
        for (int c = 0; c < 3; c++)
            C[r * 3 + c] = fmaf(A[r * 3 + 0], B[0 * 3 + c],
                           fmaf(A[r * 3 + 1], B[1 * 3 + c],
                                A[r * 3 + 2] * B[2 * 3 + c]));
}

__global__ void __launch_bounds__(512)
scan_kernel(const float* __restrict__ euler,   // (512,3)
            const float* __restrict__ c_3)     // (512,1,3)
{
    const int i    = threadIdx.x;     // view index
    const int lane = i & 31;
    const int warp = i >> 5;          // 0..15

    float a = euler[i * 3 + 0];
    float b = euler[i * 3 + 1];
    float c = euler[i * 3 + 2];
    float sa, ca, sb, cb, sc, cc;
    sincosf(a, &sa, &ca);
    sincosf(b, &sb, &cb);
    sincosf(c, &sc, &cc);

    float M[9], T[3];
    M[0] = ca * cc + sa * sb * sc;
    M[1] = -sa * cb;
    M[2] = -ca * sc + sa * sb * cc;
    M[3] = sa * cc - ca * sb * sc;
    M[4] = ca * cb;
    M[5] = -sa * sc - ca * sb * cc;
    M[6] = cb * sc;
    M[7] = sb;
    M[8] = cb * cc;
    T[0] = c_3[i * 3 + 0];
    T[1] = c_3[i * 3 + 1];
    T[2] = c_3[i * 3 + 2];

    // Phase 1: inclusive Kogge-Stone scan within each warp (earlier on left)
    #pragma unroll
    for (int d = 1; d < 32; d <<= 1) {
        float A[9], t0, t1, t2;
        #pragma unroll
        for (int k = 0; k < 9; k++) A[k] = __shfl_up_sync(0xffffffffu, M[k], d);
        t0 = __shfl_up_sync(0xffffffffu, T[0], d);
        t1 = __shfl_up_sync(0xffffffffu, T[1], d);
        t2 = __shfl_up_sync(0xffffffffu, T[2], d);
        if (lane >= d) {
            float C[9];
            mat33_mul(A, M, C);
            #pragma unroll
            for (int k = 0; k < 9; k++) M[k] = C[k];
            T[0] += t0; T[1] += t1; T[2] += t2;
        }
    }

    // Phase 2: warp 0 scans the 16 warp aggregates
    __shared__ float aggM[16][9];
    __shared__ float aggT[16][3];
    if (lane == 31) {
        #pragma unroll
        for (int k = 0; k < 9; k++) aggM[warp][k] = M[k];
        aggT[warp][0] = T[0]; aggT[warp][1] = T[1]; aggT[warp][2] = T[2];
    }
    __syncthreads();

    if (warp == 0) {
        float Ma[9] = {1.f, 0.f, 0.f, 0.f, 1.f, 0.f, 0.f, 0.f, 1.f};
        float Ta[3] = {0.f, 0.f, 0.f};
        if (lane < 16) {
            #pragma unroll
            for (int k = 0; k < 9; k++) Ma[k] = aggM[lane][k];
            Ta[0] = aggT[lane][0]; Ta[1] = aggT[lane][1]; Ta[2] = aggT[lane][2];
        }
        #pragma unroll
        for (int d = 1; d < 16; d <<= 1) {
            float A[9], t0, t1, t2;
            #pragma unroll
            for (int k = 0; k < 9; k++) A[k] = __shfl_up_sync(0xffffffffu, Ma[k], d);
            t0 = __shfl_up_sync(0xffffffffu, Ta[0], d);
            t1 = __shfl_up_sync(0xffffffffu, Ta[1], d);
            t2 = __shfl_up_sync(0xffffffffu, Ta[2], d);
            if (lane >= d && lane < 16) {
                float C[9];
                mat33_mul(A, Ma, C);
                #pragma unroll
                for (int k = 0; k < 9; k++) Ma[k] = C[k];
                Ta[0] += t0; Ta[1] += t1; Ta[2] += t2;
            }
        }
        if (lane < 16) {
            #pragma unroll
            for (int k = 0; k < 9; k++) aggM[lane][k] = Ma[k];
            aggT[lane][0] = Ta[0]; aggT[lane][1] = Ta[1]; aggT[lane][2] = Ta[2];
        }
    }
    __syncthreads();

    // Phase 3: combine — prefix of warps 0..w-1 applied on the left
    if (warp > 0) {
        float P[9], C[9];
        #pragma unroll
        for (int k = 0; k < 9; k++) P[k] = aggM[warp - 1][k];
        mat33_mul(P, M, C);
        #pragma unroll
        for (int k = 0; k < 9; k++) M[k] = C[k];
        T[0] += aggT[warp - 1][0];
        T[1] += aggT[warp - 1][1];
        T[2] += aggT[warp - 1][2];
    }

    #pragma unroll
    for (int k = 0; k < 9; k++) g_c33[i * 9 + k] = M[k];
    g_c3[i * 3 + 0] = T[0];
    g_c3[i * 3 + 1] = T[1];
    g_c3[i * 3 + 2] = T[2];
}

// ---------------------------------------------------------------------------
// Kernel 2: feat[v,s,:] = (sum_m beta[v,m]*pdepth[v,:,m,s] + pdepth0[v,:,s]) @ c33[v] + c3[v]
// Grid = 4 blocks per view x 128 threads; each thread owns one float4 column.
// Streaming inputs use __ldcs. Also writes the padded g_feat4 mirror.
// ---------------------------------------------------------------------------
__global__ void __launch_bounds__(128)
feat_kernel(const float* __restrict__ beta,      // (512,1,1,32)
            const float* __restrict__ pdepth,    // (512,3,32,2048)
            const float* __restrict__ pdepth0,   // (512,3,1,2048)
            float* __restrict__ feat)            // (512,2048,3)
{
    const int v     = blockIdx.x >> 2;
    const int chunk = blockIdx.x & 3;
    const int q     = chunk * 128 + threadIdx.x;   // quad index within view

    __shared__ float sb[N_MULTI];
    __shared__ float sR[9];
    __shared__ float sT[3];

    if (threadIdx.x < N_MULTI) sb[threadIdx.x] = beta[v * N_MULTI + threadIdx.x];
    if (threadIdx.x >= 32 && threadIdx.x < 41) sR[threadIdx.x - 32] = g_c33[v * 9 + (threadIdx.x - 32)];
    if (threadIdx.x >= 64 && threadIdx.x < 67) sT[threadIdx.x - 64] = g_c3[v * 3 + (threadIdx.x - 64)];
    __syncthreads();

    // accumulators per channel (x,y,z), 4 sifts wide
    const float4* p0 = (const float4*)(pdepth0 + (size_t)v * 3 * MAX_SIFT);
    float4 acc[3];
    #pragma unroll
    for (int ch = 0; ch < 3; ch++)
        acc[ch] = __ldcs(&p0[(size_t)ch * (MAX_SIFT / 4) + q]);

    const float4* pd = (const float4*)(pdepth + (size_t)v * 3 * N_MULTI * MAX_SIFT);
    #pragma unroll
    for (int m = 0; m < N_MULTI; m++) {
        float bm = sb[m];
        #pragma unroll
        for (int ch = 0; ch < 3; ch++) {
            float4 p = __ldcs(&pd[((size_t)ch * N_MULTI + m) * (MAX_SIFT / 4) + q]);
            acc[ch].x = fmaf(bm, p.x, acc[ch].x);
            acc[ch].y = fmaf(bm, p.y, acc[ch].y);
            acc[ch].z = fmaf(bm, p.z, acc[ch].z);
            acc[ch].w = fmaf(bm, p.w, acc[ch].w);
        }
    }

    // rotate + translate
    float o[4][3];
    const float ax[4] = {acc[0].x, acc[0].y, acc[0].z, acc[0].w};
    const float ay[4] = {acc[1].x, acc[1].y, acc[1].z, acc[1].w};
    const float az[4] = {acc[2].x, acc[2].y, acc[2].z, acc[2].w};
    #pragma unroll
    for (int e = 0; e < 4; e++) {
        o[e][0] = fmaf(ax[e], sR[0], fmaf(ay[e], sR[3], fmaf(az[e], sR[6], sT[0])));
        o[e][1] = fmaf(ax[e], sR[1], fmaf(ay[e], sR[4], fmaf(az[e], sR[7], sT[1])));
        o[e][2] = fmaf(ax[e], sR[2], fmaf(ay[e], sR[5], fmaf(az[e], sR[8], sT[2])));
    }

    // Required output layout: 12 consecutive floats (48B, 16B-aligned)
    float4* out = (float4*)(feat + (size_t)v * MAX_SIFT * 3) + (size_t)q * 3;
    out[0] = make_float4(o[0][0], o[0][1], o[0][2], o[1][0]);
    out[1] = make_float4(o[1][1], o[1][2], o[2][0], o[2][1]);
    out[2] = make_float4(o[2][2], o[3][0], o[3][1], o[3][2]);

    // Padded mirror for the gather: one aligned float4 per point
    float4* f4 = g_feat4 + (size_t)v * MAX_SIFT + (size_t)q * 4;
    f4[0] = make_float4(o[0][0], o[0][1], o[0][2], 0.f);
    f4[1] = make_float4(o[1][0], o[1][1], o[1][2], 0.f);
    f4[2] = make_float4(o[2][0], o[2][1], o[2][2], 0.f);
    f4[3] = make_float4(o[3][0], o[3][1], o[3][2], 0.f);
}

// ---------------------------------------------------------------------------
// Kernel 3: delta via aligned float4 gathers, 4 matches per thread.
// 8 independent gathers in flight per thread -> latency-hiding via MLP.
// matches is int32 (JAX x64-disabled downcast). g_feat4 is L2-resident.
// ---------------------------------------------------------------------------
__global__ void __launch_bounds__(256)
delta_kernel(const int* __restrict__ matches,   // (1e6, 2) int32
             float* __restrict__ delta)
{
    const int t    = blockIdx.x * blockDim.x + threadIdx.x;
    const int base = t * 4;                     // first match index
    if (base >= N_MATCHES) return;              // N_MATCHES % 4 == 0: full groups

    // 2 x int4 = 8 ints = 4 (i0, i1) match pairs
    const int4* m4 = (const int4*)matches;
    int4 ma = __ldg(&m4[t * 2 + 0]);
    int4 mb = __ldg(&m4[t * 2 + 1]);

    unsigned ia[4], ib[4];
    ia[0] = (unsigned)ma.x % FLAT_ROWS;  ib[0] = (unsigned)ma.y % FLAT_ROWS;
    ia[1] = (unsigned)ma.z % FLAT_ROWS;  ib[1] = (unsigned)ma.w % FLAT_ROWS;
    ia[2] = (unsigned)mb.x % FLAT_ROWS;  ib[2] = (unsigned)mb.y % FLAT_ROWS;
    ia[3] = (unsigned)mb.z % FLAT_ROWS;  ib[3] = (unsigned)mb.w % FLAT_ROWS;

    // Issue all 8 gathers before consuming any
    float4 A[4], B[4];
    #pragma unroll
    for (int k = 0; k < 4; k++) {
        A[k] = __ldg(&g_feat4[ia[k]]);
        B[k] = __ldg(&g_feat4[ib[k]]);
    }

    float out[4];
    #pragma unroll
    for (int k = 0; k < 4; k++) {
        float dx = A[k].x - B[k].x;
        float dy = A[k].y - B[k].y;
        float dz = A[k].z - B[k].z;
        out[k] = sqrtf(fmaf(dx, dx, fmaf(dy, dy, dz * dz)));
    }

    // delta is 16B-aligned (FEAT_ELEMS*4 bytes is a multiple of 16)
    float4* d4 = (float4*)(delta + base);
    d4[0] = make_float4(out[0], out[1], out[2], out[3]);
}

// ---------------------------------------------------------------------------
extern "C" void kernel_launch(void* const* d_in, const int* in_sizes, int n_in,
                              void* d_out, int out_size)
{
    const float* euler   = (const float*)d_in[0];   // c33_euler (512,3)
    const float* c_3     = (const float*)d_in[1];   // (512,1,3)
    const float* beta    = (const float*)d_in[2];   // (512,1,1,32)
    const float* pdepth  = (const float*)d_in[3];   // (512,3,32,2048)
    const float* pdepth0 = (const float*)d_in[4];   // (512,3,1,2048)
    const int*   matches = (const int*)d_in[5];     // (1e6,2) int32

    float* feat  = (float*)d_out;              // first 3,145,728 floats
    float* delta = feat + FEAT_ELEMS;          // next 1,000,000 floats

    scan_kernel<<<1, N_VIEWS>>>(euler, c_3);
    feat_kernel<<<N_VIEWS * 4, 128>>>(beta, pdepth, pdepth0, feat);

    const int dthreads = (N_MATCHES + 3) / 4;                // 250,000
    delta_kernel<<<(dthreads + 255) / 256, 256>>>(matches, delta);
}

// round 9
// speedup vs baseline: 1.1211x; 1.0244x over previous
#include <cuda_runtime.h>
#include <cuda_bf16.h>
#include <math.h>

#define N_VIEWS   512
#define N_MULTI   32
#define MAX_SIFT  2048
#define N_MATCHES 1000000

#define FEAT_ELEMS (N_VIEWS * MAX_SIFT * 3)   // 3,145,728
#define FLAT_ROWS  (N_VIEWS * MAX_SIFT)       // 1,048,576
#define FEAT_GRID  (N_VIEWS * 4)              // 2048 blocks

// Per-view cumulative rotation (row-major 3x3) and translation.
__device__ float g_c33[N_VIEWS * 9];
__device__ float g_c3[N_VIEWS * 3];
// Padded 16B-per-point mirror of feat for the delta gather (1 sector/point).
__device__ float4 g_feat4[FLAT_ROWS];
// Scan-ready flag + completion counter (reset by last feat block each replay).
__device__ volatile int g_flag;
__device__ unsigned int g_done;

__device__ __forceinline__ void mat33_mul(const float* __restrict__ A,
                                          const float* __restrict__ B,
                                          float* __restrict__ C)
{
    // C = A @ B, row-major
    #pragma unroll
    for (int r = 0; r < 3; r++)
        #pragma unroll
        for (int c = 0; c < 3; c++)
            C[r * 3 + c] = fmaf(A[r * 3 + 0], B[0 * 3 + c],
                           fmaf(A[r * 3 + 1], B[1 * 3 + c],
                                A[r * 3 + 2] * B[2 * 3 + c]));
}

__device__ __forceinline__ void build_rot(const float* __restrict__ euler,
                                          int view, float* __restrict__ R)
{
    float a = euler[view * 3 + 0];
    float b = euler[view * 3 + 1];
    float c = euler[view * 3 + 2];
    float sa, ca, sb, cb, sc, cc;
    sincosf(a, &sa, &ca);
    sincosf(b, &sb, &cb);
    sincosf(c, &sc, &cc);
    R[0] = ca * cc + sa * sb * sc;
    R[1] = -sa * cb;
    R[2] = -ca * sc + sa * sb * cc;
    R[3] = sa * cc - ca * sb * sc;
    R[4] = ca * cb;
    R[5] = -sa * sc - ca * sb * cc;
    R[6] = cb * sc;
    R[7] = sb;
    R[8] = cb * cc;
}

// Block-0 scan: 128 threads x 4 views each. Computes g_c33[v] = rot0@..@rotv
// and g_c3[v] = cumsum(c_3)[v] for all 512 views.
__device__ void do_scan_block0(const float* __restrict__ euler,
                               const float* __restrict__ c_3)
{
    const int tid  = threadIdx.x;      // 0..127
    const int lane = tid & 31;
    const int warp = tid >> 5;         // 0..3

    // Pass 1: segment totals over views [4*tid, 4*tid+3]
    float M[9] = {1.f, 0.f, 0.f, 0.f, 1.f, 0.f, 0.f, 0.f, 1.f};
    float T[3] = {0.f, 0.f, 0.f};
    #pragma unroll
    for (int k = 0; k < 4; k++) {
        const int view = tid * 4 + k;
        float R[9], C[9];
        build_rot(euler, view, R);
        mat33_mul(M, R, C);
        #pragma unroll
        for (int j = 0; j < 9; j++) M[j] = C[j];
        T[0] += c_3[view * 3 + 0];
        T[1] += c_3[view * 3 + 1];
        T[2] += c_3[view * 3 + 2];
    }

    // Intra-warp inclusive Kogge-Stone (earlier segment on the left)
    #pragma unroll
    for (int d = 1; d < 32; d <<= 1) {
        float A[9], t0, t1, t2;
        #pragma unroll
        for (int j = 0; j < 9; j++) A[j] = __shfl_up_sync(0xffffffffu, M[j], d);
        t0 = __shfl_up_sync(0xffffffffu, T[0], d);
        t1 = __shfl_up_sync(0xffffffffu, T[1], d);
        t2 = __shfl_up_sync(0xffffffffu, T[2], d);
        if (lane >= d) {
            float C[9];
            mat33_mul(A, M, C);
            #pragma unroll
            for (int j = 0; j < 9; j++) M[j] = C[j];
            T[0] += t0; T[1] += t1; T[2] += t2;
        }
    }

    // Scan the 4 warp aggregates (inclusive) in shared memory
    __shared__ float aggM[4][9];
    __shared__ float aggT[4][3];
    if (lane == 31) {
        #pragma unroll
        for (int j = 0; j < 9; j++) aggM[warp][j] = M[j];
        aggT[warp][0] = T[0]; aggT[warp][1] = T[1]; aggT[warp][2] = T[2];
    }
    __syncthreads();
    if (tid == 0) {
        // serial 3-step inclusive scan of 4 aggregates (trivial work)
        #pragma unroll
        for (int w = 1; w < 4; w++) {
            float A[9], B[9], C[9];
            #pragma unroll
            for (int j = 0; j < 9; j++) { A[j] = aggM[w - 1][j]; B[j] = aggM[w][j]; }
            mat33_mul(A, B, C);
            #pragma unroll
            for (int j = 0; j < 9; j++) aggM[w][j] = C[j];
            aggT[w][0] += aggT[w - 1][0];
            aggT[w][1] += aggT[w - 1][1];
            aggT[w][2] += aggT[w - 1][2];
        }
    }
    __syncthreads();

    // Exclusive prefix for this thread's segment
    float Mex[9], Tex[3];
    {
        float Msh[9], t0, t1, t2;
        #pragma unroll
        for (int j = 0; j < 9; j++) Msh[j] = __shfl_up_sync(0xffffffffu, M[j], 1);
        t0 = __shfl_up_sync(0xffffffffu, T[0], 1);
        t1 = __shfl_up_sync(0xffffffffu, T[1], 1);
        t2 = __shfl_up_sync(0xffffffffu, T[2], 1);

        if (lane == 0) {
            if (warp == 0) {
                Mex[0] = 1.f; Mex[1] = 0.f; Mex[2] = 0.f;
                Mex[3] = 0.f; Mex[4] = 1.f; Mex[5] = 0.f;
                Mex[6] = 0.f; Mex[7] = 0.f; Mex[8] = 1.f;
                Tex[0] = Tex[1] = Tex[2] = 0.f;
            } else {
                #pragma unroll
                for (int j = 0; j < 9; j++) Mex[j] = aggM[warp - 1][j];
                Tex[0] = aggT[warp - 1][0];
                Tex[1] = aggT[warp - 1][1];
                Tex[2] = aggT[warp - 1][2];
            }
        } else {
            if (warp == 0) {
                #pragma unroll
                for (int j = 0; j < 9; j++) Mex[j] = Msh[j];
                Tex[0] = t0; Tex[1] = t1; Tex[2] = t2;
            } else {
                float P[9];
                #pragma unroll
                for (int j = 0; j < 9; j++) P[j] = aggM[warp - 1][j];
                mat33_mul(P, Msh, Mex);
                Tex[0] = t0 + aggT[warp - 1][0];
                Tex[1] = t1 + aggT[warp - 1][1];
                Tex[2] = t2 + aggT[warp - 1][2];
            }
        }
    }

    // Pass 2: rescan segment, emitting per-view prefixes
    float P[9] = {Mex[0], Mex[1], Mex[2], Mex[3], Mex[4], Mex[5], Mex[6], Mex[7], Mex[8]};
    float Tp[3] = {Tex[0], Tex[1], Tex[2]};
    #pragma unroll
    for (int k = 0; k < 4; k++) {
        const int view = tid * 4 + k;
        float R[9], C[9];
        build_rot(euler, view, R);
        mat33_mul(P, R, C);
        #pragma unroll
        for (int j = 0; j < 9; j++) P[j] = C[j];
        Tp[0] += c_3[view * 3 + 0];
        Tp[1] += c_3[view * 3 + 1];
        Tp[2] += c_3[view * 3 + 2];
        #pragma unroll
        for (int j = 0; j < 9; j++) g_c33[view * 9 + j] = P[j];
        g_c3[view * 3 + 0] = Tp[0];
        g_c3[view * 3 + 1] = Tp[1];
        g_c3[view * 3 + 2] = Tp[2];
    }
}

// ---------------------------------------------------------------------------
// Fused feat kernel. Block 0 computes the scan first and publishes a flag;
// other blocks spin (thread 0 only) until the flag is set, then stream.
// The last block to finish resets flag/counter so every graph replay starts
// from the same state.
// ---------------------------------------------------------------------------
__global__ void __launch_bounds__(128)
feat_kernel(const float* __restrict__ euler,     // (512,3)
            const float* __restrict__ c_3,       // (512,1,3)
            const float* __restrict__ beta,      // (512,1,1,32)
            const float* __restrict__ pdepth,    // (512,3,32,2048)
            const float* __restrict__ pdepth0,   // (512,3,1,2048)
            float* __restrict__ feat)            // (512,2048,3)
{
    const int bid   = blockIdx.x;
    const int v     = bid >> 2;
    const int chunk = bid & 3;
    const int tid   = threadIdx.x;
    const int q     = chunk * 128 + tid;   // quad index within view

    if (bid == 0) {
        do_scan_block0(euler, c_3);
        __syncthreads();                   // all scan writes done
        if (tid == 0) {
            __threadfence();               // publish g_c33/g_c3
            g_flag = 1;
        }
        __syncthreads();
    } else {
        if (tid == 0) {
            while (g_flag == 0) { __nanosleep(64); }
            __threadfence();               // acquire: order subsequent reads
        }
        __syncthreads();
    }

    __shared__ float sb[N_MULTI];
    __shared__ float sR[9];
    __shared__ float sT[3];

    if (tid < N_MULTI) sb[tid] = beta[v * N_MULTI + tid];
    if (tid >= 32 && tid < 41) sR[tid - 32] = g_c33[v * 9 + (tid - 32)];
    if (tid >= 64 && tid < 67) sT[tid - 64] = g_c3[v * 3 + (tid - 64)];
    __syncthreads();

    // accumulators per channel (x,y,z), 4 sifts wide
    const float4* p0 = (const float4*)(pdepth0 + (size_t)v * 3 * MAX_SIFT);
    float4 acc[3];
    #pragma unroll
    for (int ch = 0; ch < 3; ch++)
        acc[ch] = __ldcs(&p0[(size_t)ch * (MAX_SIFT / 4) + q]);

    const float4* pd = (const float4*)(pdepth + (size_t)v * 3 * N_MULTI * MAX_SIFT);
    #pragma unroll
    for (int m = 0; m < N_MULTI; m++) {
        float bm = sb[m];
        #pragma unroll
        for (int ch = 0; ch < 3; ch++) {
            float4 p = __ldcs(&pd[((size_t)ch * N_MULTI + m) * (MAX_SIFT / 4) + q]);
            acc[ch].x = fmaf(bm, p.x, acc[ch].x);
            acc[ch].y = fmaf(bm, p.y, acc[ch].y);
            acc[ch].z = fmaf(bm, p.z, acc[ch].z);
            acc[ch].w = fmaf(bm, p.w, acc[ch].w);
        }
    }

    // rotate + translate
    float o[4][3];
    const float ax[4] = {acc[0].x, acc[0].y, acc[0].z, acc[0].w};
    const float ay[4] = {acc[1].x, acc[1].y, acc[1].z, acc[1].w};
    const float az[4] = {acc[2].x, acc[2].y, acc[2].z, acc[2].w};
    #pragma unroll
    for (int e = 0; e < 4; e++) {
        o[e][0] = fmaf(ax[e], sR[0], fmaf(ay[e], sR[3], fmaf(az[e], sR[6], sT[0])));
        o[e][1] = fmaf(ax[e], sR[1], fmaf(ay[e], sR[4], fmaf(az[e], sR[7], sT[1])));
        o[e][2] = fmaf(ax[e], sR[2], fmaf(ay[e], sR[5], fmaf(az[e], sR[8], sT[2])));
    }

    // Required output layout: 12 consecutive floats (48B, 16B-aligned)
    float4* out = (float4*)(feat + (size_t)v * MAX_SIFT * 3) + (size_t)q * 3;
    out[0] = make_float4(o[0][0], o[0][1], o[0][2], o[1][0]);
    out[1] = make_float4(o[1][1], o[1][2], o[2][0], o[2][1]);
    out[2] = make_float4(o[2][2], o[3][0], o[3][1], o[3][2]);

    // Padded mirror for the gather: one aligned float4 per point
    float4* f4 = g_feat4 + (size_t)v * MAX_SIFT + (size_t)q * 4;
    f4[0] = make_float4(o[0][0], o[0][1], o[0][2], 0.f);
    f4[1] = make_float4(o[1][0], o[1][1], o[1][2], 0.f);
    f4[2] = make_float4(o[2][0], o[2][1], o[2][2], 0.f);
    f4[3] = make_float4(o[3][0], o[3][1], o[3][2], 0.f);

    // Replay-state reset: last block to finish clears flag + counter.
    __syncthreads();
    if (tid == 0) {
        unsigned int done = atomicAdd(&g_done, 1u);
        if (done == FEAT_GRID - 1) {
            g_flag = 0;
            g_done = 0u;
        }
    }
}

// ---------------------------------------------------------------------------
// delta via aligned float4 gathers, 4 matches per thread (8 gathers in flight).
// matches is int32 (JAX x64-disabled downcast). g_feat4 is L2-resident.
// ---------------------------------------------------------------------------
__global__ void __launch_bounds__(256)
delta_kernel(const int* __restrict__ matches,   // (1e6, 2) int32
             float* __restrict__ delta)
{
    const int t    = blockIdx.x * blockDim.x + threadIdx.x;
    const int base = t * 4;
    if (base >= N_MATCHES) return;              // N_MATCHES % 4 == 0

    const int4* m4 = (const int4*)matches;
    int4 ma = __ldg(&m4[t * 2 + 0]);
    int4 mb = __ldg(&m4[t * 2 + 1]);

    unsigned ia[4], ib[4];
    ia[0] = (unsigned)ma.x % FLAT_ROWS;  ib[0] = (unsigned)ma.y % FLAT_ROWS;
    ia[1] = (unsigned)ma.z % FLAT_ROWS;  ib[1] = (unsigned)ma.w % FLAT_ROWS;
    ia[2] = (unsigned)mb.x % FLAT_ROWS;  ib[2] = (unsigned)mb.y % FLAT_ROWS;
    ia[3] = (unsigned)mb.z % FLAT_ROWS;  ib[3] = (unsigned)mb.w % FLAT_ROWS;

    float4 A[4], B[4];
    #pragma unroll
    for (int k = 0; k < 4; k++) {
        A[k] = __ldg(&g_feat4[ia[k]]);
        B[k] = __ldg(&g_feat4[ib[k]]);
    }

    float out[4];
    #pragma unroll
    for (int k = 0; k < 4; k++) {
        float dx = A[k].x - B[k].x;
        float dy = A[k].y - B[k].y;
        float dz = A[k].z - B[k].z;
        out[k] = sqrtf(fmaf(dx, dx, fmaf(dy, dy, dz * dz)));
    }

    float4* d4 = (float4*)(delta + base);
    d4[0] = make_float4(out[0], out[1], out[2], out[3]);
}

// ---------------------------------------------------------------------------
extern "C" void kernel_launch(void* const* d_in, const int* in_sizes, int n_in,
                              void* d_out, int out_size)
{
    const float* euler   = (const float*)d_in[0];   // c33_euler (512,3)
    const float* c_3     = (const float*)d_in[1];   // (512,1,3)
    const float* beta    = (const float*)d_in[2];   // (512,1,1,32)
    const float* pdepth  = (const float*)d_in[3];   // (512,3,32,2048)
    const float* pdepth0 = (const float*)d_in[4];   // (512,3,1,2048)
    const int*   matches = (const int*)d_in[5];     // (1e6,2) int32

    float* feat  = (float*)d_out;              // first 3,145,728 floats
    float* delta = feat + FEAT_ELEMS;          // next 1,000,000 floats

    feat_kernel<<<FEAT_GRID, 128>>>(euler, c_3, beta, pdepth, pdepth0, feat);

    const int dthreads = (N_MATCHES + 3) / 4;                // 250,000
    delta_kernel<<<(dthreads + 255) / 256, 256>>>(matches, delta);
}

// round 10
// speedup vs baseline: 1.1224x; 1.0011x over previous
#include <cuda_runtime.h>
#include <cuda_bf16.h>
#include <math.h>

#define N_VIEWS   512
#define N_MULTI   32
#define MAX_SIFT  2048
#define N_MATCHES 1000000

#define FEAT_ELEMS (N_VIEWS * MAX_SIFT * 3)   // 3,145,728
#define FLAT_ROWS  (N_VIEWS * MAX_SIFT)       // 1,048,576
#define FEAT_GRID  (N_VIEWS * 4)              // 2048 blocks

// Per-view cumulative rotation (row-major 3x3) and translation.
__device__ float g_c33[N_VIEWS * 9];
__device__ float g_c3[N_VIEWS * 3];
// Padded 16B-per-point mirror of feat for the delta gather (1 sector/point).
__device__ float4 g_feat4[FLAT_ROWS];
// Scan-ready flag + completion counter (reset by last feat block each replay).
__device__ volatile int g_flag;
__device__ unsigned int g_done;

__device__ __forceinline__ void mat33_mul(const float* __restrict__ A,
                                          const float* __restrict__ B,
                                          float* __restrict__ C)
{
    // C = A @ B, row-major
    #pragma unroll
    for (int r = 0; r < 3; r++)
        #pragma unroll
        for (int c = 0; c < 3; c++)
            C[r * 3 + c] = fmaf(A[r * 3 + 0], B[0 * 3 + c],
                           fmaf(A[r * 3 + 1], B[1 * 3 + c],
                                A[r * 3 + 2] * B[2 * 3 + c]));
}

__device__ __forceinline__ void build_rot(const float* __restrict__ euler,
                                          int view, float* __restrict__ R)
{
    float a = euler[view * 3 + 0];
    float b = euler[view * 3 + 1];
    float c = euler[view * 3 + 2];
    float sa, ca, sb, cb, sc, cc;
    sincosf(a, &sa, &ca);
    sincosf(b, &sb, &cb);
    sincosf(c, &sc, &cc);
    R[0] = ca * cc + sa * sb * sc;
    R[1] = -sa * cb;
    R[2] = -ca * sc + sa * sb * cc;
    R[3] = sa * cc - ca * sb * sc;
    R[4] = ca * cb;
    R[5] = -sa * sc - ca * sb * cc;
    R[6] = cb * sc;
    R[7] = sb;
    R[8] = cb * cc;
}

// Block-0 scan: 128 threads x 4 views each. Computes g_c33[v] = rot0@..@rotv
// and g_c3[v] = cumsum(c_3)[v] for all 512 views.
__device__ void do_scan_block0(const float* __restrict__ euler,
                               const float* __restrict__ c_3)
{
    const int tid  = threadIdx.x;      // 0..127
    const int lane = tid & 31;
    const int warp = tid >> 5;         // 0..3

    // Pass 1: segment totals over views [4*tid, 4*tid+3]
    float M[9] = {1.f, 0.f, 0.f, 0.f, 1.f, 0.f, 0.f, 0.f, 1.f};
    float T[3] = {0.f, 0.f, 0.f};
    #pragma unroll
    for (int k = 0; k < 4; k++) {
        const int view = tid * 4 + k;
        float R[9], C[9];
        build_rot(euler, view, R);
        mat33_mul(M, R, C);
        #pragma unroll
        for (int j = 0; j < 9; j++) M[j] = C[j];
        T[0] += c_3[view * 3 + 0];
        T[1] += c_3[view * 3 + 1];
        T[2] += c_3[view * 3 + 2];
    }

    // Intra-warp inclusive Kogge-Stone (earlier segment on the left)
    #pragma unroll
    for (int d = 1; d < 32; d <<= 1) {
        float A[9], t0, t1, t2;
        #pragma unroll
        for (int j = 0; j < 9; j++) A[j] = __shfl_up_sync(0xffffffffu, M[j], d);
        t0 = __shfl_up_sync(0xffffffffu, T[0], d);
        t1 = __shfl_up_sync(0xffffffffu, T[1], d);
        t2 = __shfl_up_sync(0xffffffffu, T[2], d);
        if (lane >= d) {
            float C[9];
            mat33_mul(A, M, C);
            #pragma unroll
            for (int j = 0; j < 9; j++) M[j] = C[j];
            T[0] += t0; T[1] += t1; T[2] += t2;
        }
    }

    // Scan the 4 warp aggregates (inclusive) in shared memory
    __shared__ float aggM[4][9];
    __shared__ float aggT[4][3];
    if (lane == 31) {
        #pragma unroll
        for (int j = 0; j < 9; j++) aggM[warp][j] = M[j];
        aggT[warp][0] = T[0]; aggT[warp][1] = T[1]; aggT[warp][2] = T[2];
    }
    __syncthreads();
    if (tid == 0) {
        #pragma unroll
        for (int w = 1; w < 4; w++) {
            float A[9], B[9], C[9];
            #pragma unroll
            for (int j = 0; j < 9; j++) { A[j] = aggM[w - 1][j]; B[j] = aggM[w][j]; }
            mat33_mul(A, B, C);
            #pragma unroll
            for (int j = 0; j < 9; j++) aggM[w][j] = C[j];
            aggT[w][0] += aggT[w - 1][0];
            aggT[w][1] += aggT[w - 1][1];
            aggT[w][2] += aggT[w - 1][2];
        }
    }
    __syncthreads();

    // Exclusive prefix for this thread's segment
    float Mex[9], Tex[3];
    {
        float Msh[9], t0, t1, t2;
        #pragma unroll
        for (int j = 0; j < 9; j++) Msh[j] = __shfl_up_sync(0xffffffffu, M[j], 1);
        t0 = __shfl_up_sync(0xffffffffu, T[0], 1);
        t1 = __shfl_up_sync(0xffffffffu, T[1], 1);
        t2 = __shfl_up_sync(0xffffffffu, T[2], 1);

        if (lane == 0) {
            if (warp == 0) {
                Mex[0] = 1.f; Mex[1] = 0.f; Mex[2] = 0.f;
                Mex[3] = 0.f; Mex[4] = 1.f; Mex[5] = 0.f;
                Mex[6] = 0.f; Mex[7] = 0.f; Mex[8] = 1.f;
                Tex[0] = Tex[1] = Tex[2] = 0.f;
            } else {
                #pragma unroll
                for (int j = 0; j < 9; j++) Mex[j] = aggM[warp - 1][j];
                Tex[0] = aggT[warp - 1][0];
                Tex[1] = aggT[warp - 1][1];
                Tex[2] = aggT[warp - 1][2];
            }
        } else {
            if (warp == 0) {
                #pragma unroll
                for (int j = 0; j < 9; j++) Mex[j] = Msh[j];
                Tex[0] = t0; Tex[1] = t1; Tex[2] = t2;
            } else {
                float P[9];
                #pragma unroll
                for (int j = 0; j < 9; j++) P[j] = aggM[warp - 1][j];
                mat33_mul(P, Msh, Mex);
                Tex[0] = t0 + aggT[warp - 1][0];
                Tex[1] = t1 + aggT[warp - 1][1];
                Tex[2] = t2 + aggT[warp - 1][2];
            }
        }
    }

    // Pass 2: rescan segment, emitting per-view prefixes
    float P[9] = {Mex[0], Mex[1], Mex[2], Mex[3], Mex[4], Mex[5], Mex[6], Mex[7], Mex[8]};
    float Tp[3] = {Tex[0], Tex[1], Tex[2]};
    #pragma unroll
    for (int k = 0; k < 4; k++) {
        const int view = tid * 4 + k;
        float R[9], C[9];
        build_rot(euler, view, R);
        mat33_mul(P, R, C);
        #pragma unroll
        for (int j = 0; j < 9; j++) P[j] = C[j];
        Tp[0] += c_3[view * 3 + 0];
        Tp[1] += c_3[view * 3 + 1];
        Tp[2] += c_3[view * 3 + 2];
        #pragma unroll
        for (int j = 0; j < 9; j++) g_c33[view * 9 + j] = P[j];
        g_c3[view * 3 + 0] = Tp[0];
        g_c3[view * 3 + 1] = Tp[1];
        g_c3[view * 3 + 2] = Tp[2];
    }
}

// ---------------------------------------------------------------------------
// Fused feat kernel. Block 0 computes the scan first and publishes a flag;
// other blocks spin (thread 0 only) until the flag is set, then stream.
// Last-finishing block resets flag/counter for clean graph replays.
// ---------------------------------------------------------------------------
__global__ void __launch_bounds__(128)
feat_kernel(const float* __restrict__ euler,     // (512,3)
            const float* __restrict__ c_3,       // (512,1,3)
            const float* __restrict__ beta,      // (512,1,1,32)
            const float* __restrict__ pdepth,    // (512,3,32,2048)
            const float* __restrict__ pdepth0,   // (512,3,1,2048)
            float* __restrict__ feat)            // (512,2048,3)
{
    const int bid   = blockIdx.x;
    const int v     = bid >> 2;
    const int chunk = bid & 3;
    const int tid   = threadIdx.x;
    const int q     = chunk * 128 + tid;   // quad index within view

    __shared__ float sb[N_MULTI];
    __shared__ float sR[9];
    __shared__ float sT[3];

    if (tid < N_MULTI) sb[tid] = beta[v * N_MULTI + tid];   // independent of scan

    if (bid == 0) {
        do_scan_block0(euler, c_3);
        __syncthreads();                   // all scan writes done
        if (tid == 0) {
            __threadfence();               // publish g_c33/g_c3
            g_flag = 1;
        }
        __syncthreads();
    } else {
        if (tid == 0) {
            while (g_flag == 0) { __nanosleep(64); }
            __threadfence();               // acquire: order subsequent reads
        }
        __syncthreads();
    }

    if (tid >= 32 && tid < 41) sR[tid - 32] = g_c33[v * 9 + (tid - 32)];
    if (tid >= 64 && tid < 67) sT[tid - 64] = g_c3[v * 3 + (tid - 64)];
    __syncthreads();

    // accumulators per channel (x,y,z), 4 sifts wide
    const float4* p0 = (const float4*)(pdepth0 + (size_t)v * 3 * MAX_SIFT);
    float4 acc[3];
    #pragma unroll
    for (int ch = 0; ch < 3; ch++)
        acc[ch] = __ldcs(&p0[(size_t)ch * (MAX_SIFT / 4) + q]);

    const float4* pd = (const float4*)(pdepth + (size_t)v * 3 * N_MULTI * MAX_SIFT);
    #pragma unroll
    for (int m = 0; m < N_MULTI; m++) {
        float bm = sb[m];
        #pragma unroll
        for (int ch = 0; ch < 3; ch++) {
            float4 p = __ldcs(&pd[((size_t)ch * N_MULTI + m) * (MAX_SIFT / 4) + q]);
            acc[ch].x = fmaf(bm, p.x, acc[ch].x);
            acc[ch].y = fmaf(bm, p.y, acc[ch].y);
            acc[ch].z = fmaf(bm, p.z, acc[ch].z);
            acc[ch].w = fmaf(bm, p.w, acc[ch].w);
        }
    }

    // rotate + translate
    float o[4][3];
    const float ax[4] = {acc[0].x, acc[0].y, acc[0].z, acc[0].w};
    const float ay[4] = {acc[1].x, acc[1].y, acc[1].z, acc[1].w};
    const float az[4] = {acc[2].x, acc[2].y, acc[2].z, acc[2].w};
    #pragma unroll
    for (int e = 0; e < 4; e++) {
        o[e][0] = fmaf(ax[e], sR[0], fmaf(ay[e], sR[3], fmaf(az[e], sR[6], sT[0])));
        o[e][1] = fmaf(ax[e], sR[1], fmaf(ay[e], sR[4], fmaf(az[e], sR[7], sT[1])));
        o[e][2] = fmaf(ax[e], sR[2], fmaf(ay[e], sR[5], fmaf(az[e], sR[8], sT[2])));
    }

    // Required output layout: 12 consecutive floats (48B, 16B-aligned)
    float4* out = (float4*)(feat + (size_t)v * MAX_SIFT * 3) + (size_t)q * 3;
    out[0] = make_float4(o[0][0], o[0][1], o[0][2], o[1][0]);
    out[1] = make_float4(o[1][1], o[1][2], o[2][0], o[2][1]);
    out[2] = make_float4(o[2][2], o[3][0], o[3][1], o[3][2]);

    // Padded mirror for the gather: one aligned float4 per point
    float4* f4 = g_feat4 + (size_t)v * MAX_SIFT + (size_t)q * 4;
    f4[0] = make_float4(o[0][0], o[0][1], o[0][2], 0.f);
    f4[1] = make_float4(o[1][0], o[1][1], o[1][2], 0.f);
    f4[2] = make_float4(o[2][0], o[2][1], o[2][2], 0.f);
    f4[3] = make_float4(o[3][0], o[3][1], o[3][2], 0.f);

    // Replay-state reset: last block to finish clears flag + counter.
    __syncthreads();
    if (tid == 0) {
        unsigned int done = atomicAdd(&g_done, 1u);
        if (done == FEAT_GRID - 1) {
            g_flag = 0;
            g_done = 0u;
        }
    }
}

// ---------------------------------------------------------------------------
// delta via aligned float4 gathers, 2 matches per thread (4 gathers in
// flight) x 500k threads: balances per-thread MLP against occupancy/tail.
// matches is int32 (JAX x64-disabled downcast). g_feat4 is L2-resident.
// ---------------------------------------------------------------------------
__global__ void __launch_bounds__(256)
delta_kernel(const int* __restrict__ matches,   // (1e6, 2) int32
             float* __restrict__ delta)
{
    const int t    = blockIdx.x * blockDim.x + threadIdx.x;
    const int base = t * 2;
    if (base >= N_MATCHES) return;              // N_MATCHES % 2 == 0

    // one int4 = 2 (i0, i1) match pairs
    int4 mp = __ldg(&((const int4*)matches)[t]);

    unsigned ia0 = (unsigned)mp.x % FLAT_ROWS;
    unsigned ib0 = (unsigned)mp.y % FLAT_ROWS;
    unsigned ia1 = (unsigned)mp.z % FLAT_ROWS;
    unsigned ib1 = (unsigned)mp.w % FLAT_ROWS;

    float4 A0 = __ldg(&g_feat4[ia0]);
    float4 B0 = __ldg(&g_feat4[ib0]);
    float4 A1 = __ldg(&g_feat4[ia1]);
    float4 B1 = __ldg(&g_feat4[ib1]);

    float dx0 = A0.x - B0.x, dy0 = A0.y - B0.y, dz0 = A0.z - B0.z;
    float dx1 = A1.x - B1.x, dy1 = A1.y - B1.y, dz1 = A1.z - B1.z;

    float2 out;
    out.x = sqrtf(fmaf(dx0, dx0, fmaf(dy0, dy0, dz0 * dz0)));
    out.y = sqrtf(fmaf(dx1, dx1, fmaf(dy1, dy1, dz1 * dz1)));

    // delta is 8B-aligned at even offsets
    *(float2*)(delta + base) = out;
}

// ---------------------------------------------------------------------------
extern "C" void kernel_launch(void* const* d_in, const int* in_sizes, int n_in,
                              void* d_out, int out_size)
{
    const float* euler   = (const float*)d_in[0];   // c33_euler (512,3)
    const float* c_3     = (const float*)d_in[1];   // (512,1,3)
    const float* beta    = (const float*)d_in[2];   // (512,1,1,32)
    const float* pdepth  = (const float*)d_in[3];   // (512,3,32,2048)
    const float* pdepth0 = (const float*)d_in[4];   // (512,3,1,2048)
    const int*   matches = (const int*)d_in[5];     // (1e6,2) int32

    float* feat  = (float*)d_out;              // first 3,145,728 floats
    float* delta = feat + FEAT_ELEMS;          // next 1,000,000 floats

    feat_kernel<<<FEAT_GRID, 128>>>(euler, c_3, beta, pdepth, pdepth0, feat);

    const int dthreads = (N_MATCHES + 1) / 2;                // 500,000
    delta_kernel<<<(dthreads + 255) / 256, 256>>>(matches, delta);
}

// round 11
// speedup vs baseline: 1.1776x; 1.0492x over previous
#include <cuda_runtime.h>
#include <cuda_bf16.h>
#include <math.h>

#define N_VIEWS   512
#define N_MULTI   32
#define MAX_SIFT  2048
#define N_MATCHES 1000000

#define FEAT_ELEMS (N_VIEWS * MAX_SIFT * 3)   // 3,145,728
#define FLAT_ROWS  (N_VIEWS * MAX_SIFT)       // 1,048,576
#define FEAT_GRID  (N_VIEWS * 4)              // 2048 blocks

// Per-view cumulative rotation (row-major 3x3) and translation.
__device__ float g_c33[N_VIEWS * 9];
__device__ float g_c3[N_VIEWS * 3];
// Padded 16B-per-point mirror of feat for the delta gather (1 sector/point).
__device__ float4 g_feat4[FLAT_ROWS];
// Scan-ready flag + completion counter (reset by last feat block each replay).
__device__ volatile int g_flag;
__device__ unsigned int g_done;

__device__ __forceinline__ void mat33_mul(const float* __restrict__ A,
                                          const float* __restrict__ B,
                                          float* __restrict__ C)
{
    // C = A @ B, row-major
    #pragma unroll
    for (int r = 0; r < 3; r++)
        #pragma unroll
        for (int c = 0; c < 3; c++)
            C[r * 3 + c] = fmaf(A[r * 3 + 0], B[0 * 3 + c],
                           fmaf(A[r * 3 + 1], B[1 * 3 + c],
                                A[r * 3 + 2] * B[2 * 3 + c]));
}

__device__ __forceinline__ void build_rot(const float* __restrict__ euler,
                                          int view, float* __restrict__ R)
{
    float a = euler[view * 3 + 0];
    float b = euler[view * 3 + 1];
    float c = euler[view * 3 + 2];
    float sa, ca, sb, cb, sc, cc;
    sincosf(a, &sa, &ca);
    sincosf(b, &sb, &cb);
    sincosf(c, &sc, &cc);
    R[0] = ca * cc + sa * sb * sc;
    R[1] = -sa * cb;
    R[2] = -ca * sc + sa * sb * cc;
    R[3] = sa * cc - ca * sb * sc;
    R[4] = ca * cb;
    R[5] = -sa * sc - ca * sb * cc;
    R[6] = cb * sc;
    R[7] = sb;
    R[8] = cb * cc;
}

// Block-0 scan: 128 threads x 4 views each. Computes g_c33[v] = rot0@..@rotv
// and g_c3[v] = cumsum(c_3)[v] for all 512 views.
__device__ void do_scan_block0(const float* __restrict__ euler,
                               const float* __restrict__ c_3)
{
    const int tid  = threadIdx.x;      // 0..127
    const int lane = tid & 31;
    const int warp = tid >> 5;         // 0..3

    // Pass 1: segment totals over views [4*tid, 4*tid+3]
    float M[9] = {1.f, 0.f, 0.f, 0.f, 1.f, 0.f, 0.f, 0.f, 1.f};
    float T[3] = {0.f, 0.f, 0.f};
    #pragma unroll
    for (int k = 0; k < 4; k++) {
        const int view = tid * 4 + k;
        float R[9], C[9];
        build_rot(euler, view, R);
        mat33_mul(M, R, C);
        #pragma unroll
        for (int j = 0; j < 9; j++) M[j] = C[j];
        T[0] += c_3[view * 3 + 0];
        T[1] += c_3[view * 3 + 1];
        T[2] += c_3[view * 3 + 2];
    }

    // Intra-warp inclusive Kogge-Stone (earlier segment on the left)
    #pragma unroll
    for (int d = 1; d < 32; d <<= 1) {
        float A[9], t0, t1, t2;
        #pragma unroll
        for (int j = 0; j < 9; j++) A[j] = __shfl_up_sync(0xffffffffu, M[j], d);
        t0 = __shfl_up_sync(0xffffffffu, T[0], d);
        t1 = __shfl_up_sync(0xffffffffu, T[1], d);
        t2 = __shfl_up_sync(0xffffffffu, T[2], d);
        if (lane >= d) {
            float C[9];
            mat33_mul(A, M, C);
            #pragma unroll
            for (int j = 0; j < 9; j++) M[j] = C[j];
            T[0] += t0; T[1] += t1; T[2] += t2;
        }
    }

    // Scan the 4 warp aggregates (inclusive) in shared memory
    __shared__ float aggM[4][9];
    __shared__ float aggT[4][3];
    if (lane == 31) {
        #pragma unroll
        for (int j = 0; j < 9; j++) aggM[warp][j] = M[j];
        aggT[warp][0] = T[0]; aggT[warp][1] = T[1]; aggT[warp][2] = T[2];
    }
    __syncthreads();
    if (tid == 0) {
        #pragma unroll
        for (int w = 1; w < 4; w++) {
            float A[9], B[9], C[9];
            #pragma unroll
            for (int j = 0; j < 9; j++) { A[j] = aggM[w - 1][j]; B[j] = aggM[w][j]; }
            mat33_mul(A, B, C);
            #pragma unroll
            for (int j = 0; j < 9; j++) aggM[w][j] = C[j];
            aggT[w][0] += aggT[w - 1][0];
            aggT[w][1] += aggT[w - 1][1];
            aggT[w][2] += aggT[w - 1][2];
        }
    }
    __syncthreads();

    // Exclusive prefix for this thread's segment
    float Mex[9], Tex[3];
    {
        float Msh[9], t0, t1, t2;
        #pragma unroll
        for (int j = 0; j < 9; j++) Msh[j] = __shfl_up_sync(0xffffffffu, M[j], 1);
        t0 = __shfl_up_sync(0xffffffffu, T[0], 1);
        t1 = __shfl_up_sync(0xffffffffu, T[1], 1);
        t2 = __shfl_up_sync(0xffffffffu, T[2], 1);

        if (lane == 0) {
            if (warp == 0) {
                Mex[0] = 1.f; Mex[1] = 0.f; Mex[2] = 0.f;
                Mex[3] = 0.f; Mex[4] = 1.f; Mex[5] = 0.f;
                Mex[6] = 0.f; Mex[7] = 0.f; Mex[8] = 1.f;
                Tex[0] = Tex[1] = Tex[2] = 0.f;
            } else {
                #pragma unroll
                for (int j = 0; j < 9; j++) Mex[j] = aggM[warp - 1][j];
                Tex[0] = aggT[warp - 1][0];
                Tex[1] = aggT[warp - 1][1];
                Tex[2] = aggT[warp - 1][2];
            }
        } else {
            if (warp == 0) {
                #pragma unroll
                for (int j = 0; j < 9; j++) Mex[j] = Msh[j];
                Tex[0] = t0; Tex[1] = t1; Tex[2] = t2;
            } else {
                float P[9];
                #pragma unroll
                for (int j = 0; j < 9; j++) P[j] = aggM[warp - 1][j];
                mat33_mul(P, Msh, Mex);
                Tex[0] = t0 + aggT[warp - 1][0];
                Tex[1] = t1 + aggT[warp - 1][1];
                Tex[2] = t2 + aggT[warp - 1][2];
            }
        }
    }

    // Pass 2: rescan segment, emitting per-view prefixes
    float P[9] = {Mex[0], Mex[1], Mex[2], Mex[3], Mex[4], Mex[5], Mex[6], Mex[7], Mex[8]};
    float Tp[3] = {Tex[0], Tex[1], Tex[2]};
    #pragma unroll
    for (int k = 0; k < 4; k++) {
        const int view = tid * 4 + k;
        float R[9], C[9];
        build_rot(euler, view, R);
        mat33_mul(P, R, C);
        #pragma unroll
        for (int j = 0; j < 9; j++) P[j] = C[j];
        Tp[0] += c_3[view * 3 + 0];
        Tp[1] += c_3[view * 3 + 1];
        Tp[2] += c_3[view * 3 + 2];
        #pragma unroll
        for (int j = 0; j < 9; j++) g_c33[view * 9 + j] = P[j];
        g_c3[view * 3 + 0] = Tp[0];
        g_c3[view * 3 + 1] = Tp[1];
        g_c3[view * 3 + 2] = Tp[2];
    }
}

// ---------------------------------------------------------------------------
// Fused feat kernel — LATE scan wait. The beta-weighted accumulation is
// independent of the scan, so every block streams immediately; block 0 runs
// the scan before its stream; all blocks wait for the flag only at the
// epilogue (rotation), by which point the scan finished ~60us earlier.
// Last-finishing block resets flag/counter for clean graph replays.
// ---------------------------------------------------------------------------
__global__ void __launch_bounds__(128)
feat_kernel(const float* __restrict__ euler,     // (512,3)
            const float* __restrict__ c_3,       // (512,1,3)
            const float* __restrict__ beta,      // (512,1,1,32)
            const float* __restrict__ pdepth,    // (512,3,32,2048)
            const float* __restrict__ pdepth0,   // (512,3,1,2048)
            float* __restrict__ feat)            // (512,2048,3)
{
    const int bid   = blockIdx.x;
    const int v     = bid >> 2;
    const int chunk = bid & 3;
    const int tid   = threadIdx.x;
    const int q     = chunk * 128 + tid;   // quad index within view

    __shared__ float sb[N_MULTI];
    __shared__ float sR[9];
    __shared__ float sT[3];

    if (bid == 0) {
        // Scan first so the flag publishes ~2us into the kernel.
        do_scan_block0(euler, c_3);
        __syncthreads();                   // all scan writes done
        if (tid == 0) {
            __threadfence();               // publish g_c33/g_c3
            g_flag = 1;
        }
    }

    if (tid < N_MULTI) sb[tid] = beta[v * N_MULTI + tid];
    __syncthreads();

    // ---- Mainloop: stream pdepth, accumulate (scan-independent) ----
    const float4* p0 = (const float4*)(pdepth0 + (size_t)v * 3 * MAX_SIFT);
    float4 acc[3];
    #pragma unroll
    for (int ch = 0; ch < 3; ch++)
        acc[ch] = __ldcs(&p0[(size_t)ch * (MAX_SIFT / 4) + q]);

    const float4* pd = (const float4*)(pdepth + (size_t)v * 3 * N_MULTI * MAX_SIFT);
    #pragma unroll
    for (int m = 0; m < N_MULTI; m++) {
        float bm = sb[m];
        #pragma unroll
        for (int ch = 0; ch < 3; ch++) {
            float4 p = __ldcs(&pd[((size_t)ch * N_MULTI + m) * (MAX_SIFT / 4) + q]);
            acc[ch].x = fmaf(bm, p.x, acc[ch].x);
            acc[ch].y = fmaf(bm, p.y, acc[ch].y);
            acc[ch].z = fmaf(bm, p.z, acc[ch].z);
            acc[ch].w = fmaf(bm, p.w, acc[ch].w);
        }
    }

    // ---- Late scan wait: flag is set long before most blocks get here ----
    if (tid == 0) {
        while (g_flag == 0) { __nanosleep(64); }
        __threadfence();                   // acquire: order g_c33/g_c3 reads
    }
    __syncthreads();

    if (tid < 9)  sR[tid] = g_c33[v * 9 + tid];
    if (tid >= 32 && tid < 35) sT[tid - 32] = g_c3[v * 3 + (tid - 32)];
    __syncthreads();

    // ---- Epilogue: rotate + translate ----
    float o[4][3];
    const float ax[4] = {acc[0].x, acc[0].y, acc[0].z, acc[0].w};
    const float ay[4] = {acc[1].x, acc[1].y, acc[1].z, acc[1].w};
    const float az[4] = {acc[2].x, acc[2].y, acc[2].z, acc[2].w};
    #pragma unroll
    for (int e = 0; e < 4; e++) {
        o[e][0] = fmaf(ax[e], sR[0], fmaf(ay[e], sR[3], fmaf(az[e], sR[6], sT[0])));
        o[e][1] = fmaf(ax[e], sR[1], fmaf(ay[e], sR[4], fmaf(az[e], sR[7], sT[1])));
        o[e][2] = fmaf(ax[e], sR[2], fmaf(ay[e], sR[5], fmaf(az[e], sR[8], sT[2])));
    }

    // Required output layout: 12 consecutive floats (48B, 16B-aligned)
    float4* out = (float4*)(feat + (size_t)v * MAX_SIFT * 3) + (size_t)q * 3;
    out[0] = make_float4(o[0][0], o[0][1], o[0][2], o[1][0]);
    out[1] = make_float4(o[1][1], o[1][2], o[2][0], o[2][1]);
    out[2] = make_float4(o[2][2], o[3][0], o[3][1], o[3][2]);

    // Padded mirror for the gather: one aligned float4 per point
    float4* f4 = g_feat4 + (size_t)v * MAX_SIFT + (size_t)q * 4;
    f4[0] = make_float4(o[0][0], o[0][1], o[0][2], 0.f);
    f4[1] = make_float4(o[1][0], o[1][1], o[1][2], 0.f);
    f4[2] = make_float4(o[2][0], o[2][1], o[2][2], 0.f);
    f4[3] = make_float4(o[3][0], o[3][1], o[3][2], 0.f);

    // Replay-state reset: last block to finish clears flag + counter.
    __syncthreads();
    if (tid == 0) {
        unsigned int done = atomicAdd(&g_done, 1u);
        if (done == FEAT_GRID - 1) {
            g_flag = 0;
            g_done = 0u;
        }
    }
}

// ---------------------------------------------------------------------------
// delta via aligned float4 gathers, 2 matches per thread. At the within-LDG
// replay floor (~2.07 cyc/wavefront x 2M lane-gathers) — not worth more.
// matches is int32 (JAX x64-disabled downcast). g_feat4 is L2-resident.
// ---------------------------------------------------------------------------
__global__ void __launch_bounds__(256)
delta_kernel(const int* __restrict__ matches,   // (1e6, 2) int32
             float* __restrict__ delta)
{
    const int t    = blockIdx.x * blockDim.x + threadIdx.x;
    const int base = t * 2;
    if (base >= N_MATCHES) return;              // N_MATCHES % 2 == 0

    // one int4 = 2 (i0, i1) match pairs
    int4 mp = __ldg(&((const int4*)matches)[t]);

    unsigned ia0 = (unsigned)mp.x % FLAT_ROWS;
    unsigned ib0 = (unsigned)mp.y % FLAT_ROWS;
    unsigned ia1 = (unsigned)mp.z % FLAT_ROWS;
    unsigned ib1 = (unsigned)mp.w % FLAT_ROWS;

    float4 A0 = __ldg(&g_feat4[ia0]);
    float4 B0 = __ldg(&g_feat4[ib0]);
    float4 A1 = __ldg(&g_feat4[ia1]);
    float4 B1 = __ldg(&g_feat4[ib1]);

    float dx0 = A0.x - B0.x, dy0 = A0.y - B0.y, dz0 = A0.z - B0.z;
    float dx1 = A1.x - B1.x, dy1 = A1.y - B1.y, dz1 = A1.z - B1.z;

    float2 out;
    out.x = sqrtf(fmaf(dx0, dx0, fmaf(dy0, dy0, dz0 * dz0)));
    out.y = sqrtf(fmaf(dx1, dx1, fmaf(dy1, dy1, dz1 * dz1)));

    *(float2*)(delta + base) = out;
}

// ---------------------------------------------------------------------------
extern "C" void kernel_launch(void* const* d_in, const int* in_sizes, int n_in,
                              void* d_out, int out_size)
{
    const float* euler   = (const float*)d_in[0];   // c33_euler (512,3)
    const float* c_3     = (const float*)d_in[1];   // (512,1,3)
    const float* beta    = (const float*)d_in[2];   // (512,1,1,32)
    const float* pdepth  = (const float*)d_in[3];   // (512,3,32,2048)
    const float* pdepth0 = (const float*)d_in[4];   // (512,3,1,2048)
    const int*   matches = (const int*)d_in[5];     // (1e6,2) int32

    float* feat  = (float*)d_out;              // first 3,145,728 floats
    float* delta = feat + FEAT_ELEMS;          // next 1,000,000 floats

    feat_kernel<<<FEAT_GRID, 128>>>(euler, c_3, beta, pdepth, pdepth0, feat);

    const int dthreads = (N_MATCHES + 1) / 2;                // 500,000
    delta_kernel<<<(dthreads + 255) / 256, 256>>>(matches, delta);
}